// round 1
// baseline (speedup 1.0000x reference)
#include <cuda_runtime.h>

// Swin window attention, fused per-window kernel.
// B=32, nW=64 -> 2048 windows; N=49 tokens, C=128, H=4 heads, hd=32.
// One CTA per window, 512 threads, everything staged through shared memory.

#define NWIN 64
#define NTOK 49
#define CDIM 128
#define NHEAD 4
#define HDIM 32
#define TPB 512

// shared memory layout (in floats)
// s_xT : [128][52]  x transposed (feature-major), reused later as s_oT
// s_q  : [49][128]
// s_kT : [128][52]  k transposed (feature-major)
// s_v  : [49][128]
// s_attn:[196][52]  (H*N rows, padded to 52)
static constexpr int OFF_XT   = 0;
static constexpr int OFF_Q    = OFF_XT + 128 * 52;          // 6656
static constexpr int OFF_KT   = OFF_Q + NTOK * CDIM;        // 12928
static constexpr int OFF_V    = OFF_KT + 128 * 52;          // 19584
static constexpr int OFF_ATTN = OFF_V + NTOK * CDIM;        // 25856
static constexpr int SMEM_FLOATS = OFF_ATTN + (NHEAD * NTOK) * 52;  // 36048
static constexpr int SMEM_BYTES = SMEM_FLOATS * 4;          // 144192

__global__ __launch_bounds__(TPB, 1)
void swin_window_attn_kernel(const float* __restrict__ x_all,
                             const float* __restrict__ mask,
                             const float* __restrict__ qkv_w,
                             const float* __restrict__ qkv_b,
                             const float* __restrict__ proj_w,
                             const float* __restrict__ proj_b,
                             const float* __restrict__ rel_table,
                             float* __restrict__ out)
{
    extern __shared__ float sm[];
    float* s_xT   = sm + OFF_XT;
    float* s_q    = sm + OFF_Q;
    float* s_kT   = sm + OFF_KT;
    float* s_v    = sm + OFF_V;
    float* s_attn = sm + OFF_ATTN;
    float* s_oT   = s_xT;   // x is dead after QKV; reuse the slab

    const int tid = threadIdx.x;
    const int blk = blockIdx.x;
    const float* x  = x_all + (size_t)blk * (NTOK * CDIM);
    const float* mw = mask  + (size_t)(blk & (NWIN - 1)) * (NTOK * NTOK);

    // ---- load x, transposed: s_xT[kk][r] ----
    for (int idx = tid; idx < NTOK * CDIM; idx += TPB) {
        int r = idx >> 7;
        int kk = idx & 127;
        s_xT[kk * 52 + r] = x[idx];
    }
    __syncthreads();

    // thread -> (row group, column) mapping for the GEMM phases
    const int g     = tid >> 7;          // 0..3
    const int col   = tid & 127;         // 0..127
    const int rbase = g * 12;            // 0,12,24,36
    const int rcnt  = (g == 3) ? 13 : 12;

    // ---- phase 1: QKV GEMM  (49x384 = x[49x128] @ qkv_w[128x384]) ----
    for (int chunk = 0; chunk < 3; ++chunk) {
        const int wcol = chunk * 128 + col;
        float acc[13];
        #pragma unroll
        for (int i = 0; i < 13; ++i) acc[i] = 0.f;

        #pragma unroll 4
        for (int kk = 0; kk < 128; ++kk) {
            const float wv = __ldg(&qkv_w[kk * 384 + wcol]);
            const float4* xr = reinterpret_cast<const float4*>(&s_xT[kk * 52 + rbase]);
            const float4 a0 = xr[0];
            const float4 a1 = xr[1];
            const float4 a2 = xr[2];
            const float x12 = s_xT[kk * 52 + rbase + 12];
            acc[0]  += a0.x * wv;  acc[1]  += a0.y * wv;
            acc[2]  += a0.z * wv;  acc[3]  += a0.w * wv;
            acc[4]  += a1.x * wv;  acc[5]  += a1.y * wv;
            acc[6]  += a1.z * wv;  acc[7]  += a1.w * wv;
            acc[8]  += a2.x * wv;  acc[9]  += a2.y * wv;
            acc[10] += a2.z * wv;  acc[11] += a2.w * wv;
            acc[12] += x12 * wv;
        }
        const float bv = __ldg(&qkv_b[wcol]);
        if (chunk == 0) {            // q: row-major
            for (int i = 0; i < rcnt; ++i)
                s_q[(rbase + i) * 128 + col] = acc[i] + bv;
        } else if (chunk == 1) {     // k: transposed [feature][token]
            for (int i = 0; i < rcnt; ++i)
                s_kT[col * 52 + (rbase + i)] = acc[i] + bv;
        } else {                     // v: row-major
            for (int i = 0; i < rcnt; ++i)
                s_v[(rbase + i) * 128 + col] = acc[i] + bv;
        }
    }
    __syncthreads();

    // ---- phase 2: attention scores + rel-pos bias + shift mask ----
    const float scale = 0.17677669529663687f;   // 1/sqrt(32)
    for (int idx = tid; idx < NHEAD * NTOK * NTOK; idx += TPB) {
        const int h   = idx / (NTOK * NTOK);
        const int rem = idx - h * (NTOK * NTOK);
        const int i   = rem / NTOK;
        const int j   = rem - i * NTOK;
        const float* qr = &s_q[i * 128 + h * HDIM];        // broadcast within warp
        const float* kc = &s_kT[(h * HDIM) * 52 + j];      // lane-consecutive j
        float s = 0.f;
        #pragma unroll
        for (int d = 0; d < HDIM; ++d) s += qr[d] * kc[d * 52];
        const int yi = i / 7, xi = i - yi * 7;
        const int yj = j / 7, xj = j - yj * 7;
        const int ridx = (yi - yj + 6) * 13 + (xi - xj + 6);
        const float b = __ldg(&rel_table[ridx * NHEAD + h]);
        s_attn[(h * NTOK + i) * 52 + j] = s * scale + b + mw[rem];
    }
    __syncthreads();

    // ---- phase 3: softmax, one warp per (head, query-row) ----
    {
        const int warp = tid >> 5;
        const int lane = tid & 31;
        for (int row = warp; row < NHEAD * NTOK; row += TPB / 32) {
            float* a = &s_attn[row * 52];
            float v0 = (lane < NTOK)      ? a[lane]      : -1e30f;
            float v1 = (lane + 32 < NTOK) ? a[lane + 32] : -1e30f;
            float m = fmaxf(v0, v1);
            #pragma unroll
            for (int off = 16; off; off >>= 1)
                m = fmaxf(m, __shfl_xor_sync(0xffffffffu, m, off));
            float e0 = (lane < NTOK)      ? __expf(v0 - m) : 0.f;
            float e1 = (lane + 32 < NTOK) ? __expf(v1 - m) : 0.f;
            float ssum = e0 + e1;
            #pragma unroll
            for (int off = 16; off; off >>= 1)
                ssum += __shfl_xor_sync(0xffffffffu, ssum, off);
            const float inv = 1.0f / ssum;
            if (lane < NTOK)      a[lane]      = e0 * inv;
            if (lane + 32 < NTOK) a[lane + 32] = e1 * inv;
        }
    }
    __syncthreads();

    // ---- phase 4: attn @ v -> s_oT[c][i] (transposed for proj) ----
    for (int idx = tid; idx < NTOK * CDIM; idx += TPB) {
        const int i = idx >> 7;
        const int c = idx & 127;
        const int h = c >> 5;
        const float* ar = &s_attn[(h * NTOK + i) * 52];   // broadcast within warp
        const float* vc = &s_v[c];                         // lane-consecutive c
        float s = 0.f;
        #pragma unroll
        for (int j = 0; j < NTOK; ++j) s += ar[j] * vc[j * 128];
        s_oT[c * 52 + i] = s;
    }
    __syncthreads();

    // ---- phase 5: output projection (49x128 = o[49x128] @ proj_w[128x128]) ----
    {
        float acc[13];
        #pragma unroll
        for (int i = 0; i < 13; ++i) acc[i] = 0.f;

        #pragma unroll 4
        for (int kk = 0; kk < 128; ++kk) {
            const float wv = __ldg(&proj_w[kk * 128 + col]);
            const float4* orow = reinterpret_cast<const float4*>(&s_oT[kk * 52 + rbase]);
            const float4 a0 = orow[0];
            const float4 a1 = orow[1];
            const float4 a2 = orow[2];
            const float o12 = s_oT[kk * 52 + rbase + 12];
            acc[0]  += a0.x * wv;  acc[1]  += a0.y * wv;
            acc[2]  += a0.z * wv;  acc[3]  += a0.w * wv;
            acc[4]  += a1.x * wv;  acc[5]  += a1.y * wv;
            acc[6]  += a1.z * wv;  acc[7]  += a1.w * wv;
            acc[8]  += a2.x * wv;  acc[9]  += a2.y * wv;
            acc[10] += a2.z * wv;  acc[11] += a2.w * wv;
            acc[12] += o12 * wv;
        }
        const float bv = __ldg(&proj_b[col]);
        float* o = out + (size_t)blk * (NTOK * CDIM);
        for (int i = 0; i < rcnt; ++i)
            o[(rbase + i) * 128 + col] = acc[i] + bv;
    }
}

extern "C" void kernel_launch(void* const* d_in, const int* in_sizes, int n_in,
                              void* d_out, int out_size)
{
    const float* x      = (const float*)d_in[0];
    const float* mask   = (const float*)d_in[1];
    const float* qkv_w  = (const float*)d_in[2];
    const float* qkv_b  = (const float*)d_in[3];
    const float* proj_w = (const float*)d_in[4];
    const float* proj_b = (const float*)d_in[5];
    const float* rel    = (const float*)d_in[6];
    float* out = (float*)d_out;

    cudaFuncSetAttribute(swin_window_attn_kernel,
                         cudaFuncAttributeMaxDynamicSharedMemorySize, SMEM_BYTES);
    swin_window_attn_kernel<<<2048, TPB, SMEM_BYTES>>>(
        x, mask, qkv_w, qkv_b, proj_w, proj_b, rel, out);
}

// round 3
// speedup vs baseline: 1.1952x; 1.1952x over previous
#include <cuda_runtime.h>

// Swin window attention, fused per-window kernel, v2 (re-bench after infra failure).
// B=32, nW=64 -> 2048 windows; N=49 tokens, C=128, H=4 heads, hd=32.
// One CTA per window, 512 threads. Register-tiled, LDS-minimized.

#define NWIN 64
#define NTOK 49
#define CDIM 128
#define NHEAD 4
#define HDIM 32
#define TPB 512
#define QPITCH 130   // s_q row pitch (floats), avoids bank conflicts on strided reads

// shared memory layout (floats)
static constexpr int OFF_X    = 0;                       // [49][128], reused as s_o
static constexpr int OFF_Q    = OFF_X + NTOK * CDIM;     // 6272, [49][130]
static constexpr int OFF_KT   = OFF_Q + NTOK * QPITCH;   // 12642 -> align to 12644
static constexpr int OFF_KT_A = 12644;                   // [128][52] k transposed
static constexpr int OFF_V    = OFF_KT_A + 128 * 52;     // 19300, [49][128]
static constexpr int OFF_ATTN = OFF_V + NTOK * CDIM;     // 25572, [196][52]
static constexpr int SMEM_FLOATS = OFF_ATTN + (NHEAD * NTOK) * 52;  // 35764
static constexpr int SMEM_BYTES  = SMEM_FLOATS * 4;      // 143056

__global__ __launch_bounds__(TPB, 1)
void swin_window_attn_kernel(const float* __restrict__ x_all,
                             const float* __restrict__ mask,
                             const float* __restrict__ qkv_w,
                             const float* __restrict__ qkv_b,
                             const float* __restrict__ proj_w,
                             const float* __restrict__ proj_b,
                             const float* __restrict__ rel_table,
                             float* __restrict__ out)
{
    extern __shared__ float sm[];
    float* s_x    = sm + OFF_X;      // row-major x, later reused as s_o
    float* s_q    = sm + OFF_Q;      // [49][130]
    float* s_kT   = sm + OFF_KT_A;   // [128][52]  (feature-major, token along row)
    float* s_v    = sm + OFF_V;      // [49][128]
    float* s_attn = sm + OFF_ATTN;   // [196][52]
    float* s_o    = s_x;

    const int tid = threadIdx.x;
    const int blk = blockIdx.x;
    const float* x  = x_all + (size_t)blk * (NTOK * CDIM);
    const float* mw = mask  + (size_t)(blk & (NWIN - 1)) * (NTOK * NTOK);

    // ---- load x row-major (coalesced, vectorized) ----
    {
        const float4* xg = reinterpret_cast<const float4*>(x);
        float4* xs = reinterpret_cast<float4*>(s_x);
        for (int idx = tid; idx < NTOK * CDIM / 4; idx += TPB) xs[idx] = xg[idx];
    }
    __syncthreads();

    const int col   = tid & 127;     // output column within a 128-chunk
    const int g     = tid >> 7;      // row group 0..3
    const int rbase = g * 12;        // 0,12,24,36
    const int rcnt  = (g == 3) ? 13 : 12;

    // ---- phase 1: QKV GEMM, thread tile = 13 rows x 3 chunk-cols ----
    {
        float a0[13], a1[13], a2[13];
        #pragma unroll
        for (int i = 0; i < 13; ++i) { a0[i] = 0.f; a1[i] = 0.f; a2[i] = 0.f; }

        #pragma unroll 1
        for (int k4 = 0; k4 < 32; ++k4) {
            const int kk = k4 * 4;
            float w0[4], w1[4], w2[4];
            #pragma unroll
            for (int t = 0; t < 4; ++t) {
                const float* wr = qkv_w + (size_t)(kk + t) * 384;
                w0[t] = __ldg(&wr[col]);
                w1[t] = __ldg(&wr[128 + col]);
                w2[t] = __ldg(&wr[256 + col]);
            }
            #pragma unroll
            for (int i = 0; i < 13; ++i) {
                const float4 xv = *reinterpret_cast<const float4*>(&s_x[(rbase + i) * 128 + kk]);
                a0[i] += xv.x * w0[0] + xv.y * w0[1] + xv.z * w0[2] + xv.w * w0[3];
                a1[i] += xv.x * w1[0] + xv.y * w1[1] + xv.z * w1[2] + xv.w * w1[3];
                a2[i] += xv.x * w2[0] + xv.y * w2[1] + xv.z * w2[2] + xv.w * w2[3];
            }
        }
        const float b0 = __ldg(&qkv_b[col]);
        const float b1 = __ldg(&qkv_b[128 + col]);
        const float b2 = __ldg(&qkv_b[256 + col]);
        for (int i = 0; i < rcnt; ++i) {
            const int r = rbase + i;
            s_q[r * QPITCH + col] = a0[i] + b0;     // q row-major (pitch 130)
            s_kT[col * 52 + r]    = a1[i] + b1;     // k transposed [feature][token]
            s_v[r * 128 + col]    = a2[i] + b2;     // v row-major
        }
    }
    __syncthreads();

    // ---- phase 2: scores + bias + mask, thread = (h, i, 4 adjacent j) ----
    {
        const float scale = 0.17677669529663687f;   // 1/sqrt(32)
        for (int u = tid; u < NHEAD * NTOK * 13; u += TPB) {
            const int h   = u / (NTOK * 13);
            const int rem = u - h * (NTOK * 13);
            const int i   = rem / 13;
            const int jg  = rem - i * 13;
            const int j4  = jg * 4;

            const float* qr = &s_q[i * QPITCH + h * HDIM];
            const float* kc = &s_kT[(h * HDIM) * 52 + j4];
            float sx = 0.f, sy = 0.f, sz = 0.f, sw = 0.f;
            #pragma unroll
            for (int d = 0; d < HDIM; ++d) {
                const float qv = qr[d];
                const float4 kv = *reinterpret_cast<const float4*>(&kc[d * 52]);
                sx += qv * kv.x; sy += qv * kv.y;
                sz += qv * kv.z; sw += qv * kv.w;
            }
            float sv[4] = {sx, sy, sz, sw};
            const int yi = i / 7, xi = i - yi * 7;
            float* arow = &s_attn[(h * NTOK + i) * 52];
            const float* mrow = &mw[i * NTOK];
            #pragma unroll
            for (int jj = 0; jj < 4; ++jj) {
                const int j = j4 + jj;
                if (j < NTOK) {
                    const int yj = j / 7, xj = j - yj * 7;
                    const int ridx = (yi - yj + 6) * 13 + (xi - xj + 6);
                    const float b = __ldg(&rel_table[ridx * NHEAD + h]);
                    arow[j] = sv[jj] * scale + b + mrow[j];
                }
            }
        }
    }
    __syncthreads();

    // ---- phase 3: softmax, one warp per (head, query-row) ----
    {
        const int warp = tid >> 5;
        const int lane = tid & 31;
        for (int row = warp; row < NHEAD * NTOK; row += TPB / 32) {
            float* a = &s_attn[row * 52];
            float v0 = (lane < NTOK)      ? a[lane]      : -1e30f;
            float v1 = (lane + 32 < NTOK) ? a[lane + 32] : -1e30f;
            float m = fmaxf(v0, v1);
            #pragma unroll
            for (int off = 16; off; off >>= 1)
                m = fmaxf(m, __shfl_xor_sync(0xffffffffu, m, off));
            float e0 = (lane < NTOK)      ? __expf(v0 - m) : 0.f;
            float e1 = (lane + 32 < NTOK) ? __expf(v1 - m) : 0.f;
            float ssum = e0 + e1;
            #pragma unroll
            for (int off = 16; off; off >>= 1)
                ssum += __shfl_xor_sync(0xffffffffu, ssum, off);
            const float inv = 1.0f / ssum;
            if (lane < NTOK)      a[lane]      = e0 * inv;
            if (lane + 32 < NTOK) a[lane + 32] = e1 * inv;
        }
    }
    __syncthreads();

    // ---- phase 4: attn @ v -> s_o row-major, thread = (i, 4 adjacent c) ----
    for (int u = tid; u < NTOK * 32; u += TPB) {
        const int i  = u >> 5;
        const int cg = u & 31;
        const int c4 = cg * 4;
        const int h  = cg >> 3;
        const float* ar = &s_attn[(h * NTOK + i) * 52];
        const float* vr = &s_v[c4];
        float sx = 0.f, sy = 0.f, sz = 0.f, sw = 0.f;
        #pragma unroll 7
        for (int j = 0; j < NTOK; ++j) {
            const float av = ar[j];
            const float4 vv = *reinterpret_cast<const float4*>(&vr[j * 128]);
            sx += av * vv.x; sy += av * vv.y;
            sz += av * vv.z; sw += av * vv.w;
        }
        float* orow = &s_o[i * 128 + c4];
        orow[0] = sx; orow[1] = sy; orow[2] = sz; orow[3] = sw;
    }
    __syncthreads();

    // ---- phase 5: output projection, thread tile = 13 rows x 1 col, k4-vectorized ----
    {
        float acc[13];
        #pragma unroll
        for (int i = 0; i < 13; ++i) acc[i] = 0.f;

        #pragma unroll 1
        for (int k4 = 0; k4 < 32; ++k4) {
            const int kk = k4 * 4;
            float w[4];
            #pragma unroll
            for (int t = 0; t < 4; ++t)
                w[t] = __ldg(&proj_w[(size_t)(kk + t) * 128 + col]);
            #pragma unroll
            for (int i = 0; i < 13; ++i) {
                const float4 ov = *reinterpret_cast<const float4*>(&s_o[(rbase + i) * 128 + kk]);
                acc[i] += ov.x * w[0] + ov.y * w[1] + ov.z * w[2] + ov.w * w[3];
            }
        }
        const float bv = __ldg(&proj_b[col]);
        float* o = out + (size_t)blk * (NTOK * CDIM);
        for (int i = 0; i < rcnt; ++i)
            o[(rbase + i) * 128 + col] = acc[i] + bv;
    }
}

extern "C" void kernel_launch(void* const* d_in, const int* in_sizes, int n_in,
                              void* d_out, int out_size)
{
    const float* x      = (const float*)d_in[0];
    const float* mask   = (const float*)d_in[1];
    const float* qkv_w  = (const float*)d_in[2];
    const float* qkv_b  = (const float*)d_in[3];
    const float* proj_w = (const float*)d_in[4];
    const float* proj_b = (const float*)d_in[5];
    const float* rel    = (const float*)d_in[6];
    float* out = (float*)d_out;

    cudaFuncSetAttribute(swin_window_attn_kernel,
                         cudaFuncAttributeMaxDynamicSharedMemorySize, SMEM_BYTES);
    swin_window_attn_kernel<<<2048, TPB, SMEM_BYTES>>>(
        x, mask, qkv_w, qkv_b, proj_w, proj_b, rel, out);
}

// round 4
// speedup vs baseline: 1.3743x; 1.1498x over previous
#include <cuda_runtime.h>

// Swin window attention, fused per-window kernel, v3: packed f32x2 FFMA.
// B=32, nW=64 -> 2048 windows; N=49 tokens, C=128, H=4 heads, hd=32.
// One CTA per window, 512 threads.

#define NWIN 64
#define NTOK 49
#define CDIM 128
#define NHEAD 4
#define HDIM 32
#define TPB 512
#define QPITCH 130

using u64 = unsigned long long;

__device__ __forceinline__ void fma2(u64& d, u64 a, u64 b) {
    asm("fma.rn.f32x2 %0, %1, %2, %0;" : "+l"(d) : "l"(a), "l"(b));
}
__device__ __forceinline__ u64 pack2(float lo, float hi) {
    u64 r; asm("mov.b64 %0, {%1, %2};" : "=l"(r) : "f"(lo), "f"(hi)); return r;
}
__device__ __forceinline__ float2 unpack2(u64 v) {
    float2 r; asm("mov.b64 {%0, %1}, %2;" : "=f"(r.x), "=f"(r.y) : "l"(v)); return r;
}

// shared memory layout (floats)
static constexpr int OFF_XT   = 0;                         // [128][52] x transposed; later s_o [49][128]
static constexpr int OFF_Q    = OFF_XT + 128 * 52;         // 6656, [49][130]
static constexpr int OFF_KT   = 13028;                     // [128][52] k transposed (16B aligned)
static constexpr int OFF_V    = OFF_KT + 128 * 52;         // 19684, [49][128]
static constexpr int OFF_ATTN = OFF_V + NTOK * CDIM;       // 25956, [196][52]
static constexpr int SMEM_FLOATS = OFF_ATTN + (NHEAD * NTOK) * 52;  // 36148
static constexpr int SMEM_BYTES  = SMEM_FLOATS * 4;        // 144592

__global__ __launch_bounds__(TPB, 1)
void swin_window_attn_kernel(const float* __restrict__ x_all,
                             const float* __restrict__ mask,
                             const float* __restrict__ qkv_w,
                             const float* __restrict__ qkv_b,
                             const float* __restrict__ proj_w,
                             const float* __restrict__ proj_b,
                             const float* __restrict__ rel_table,
                             float* __restrict__ out)
{
    extern __shared__ float sm[];
    float* s_xT   = sm + OFF_XT;     // [128][52]
    float* s_q    = sm + OFF_Q;      // [49][130]
    float* s_kT   = sm + OFF_KT;     // [128][52]
    float* s_v    = sm + OFF_V;      // [49][128]
    float* s_attn = sm + OFF_ATTN;   // [196][52]
    float* s_o    = sm + OFF_XT;     // alias: x dead after phase 1, o is [49][128]

    const int tid = threadIdx.x;
    const int blk = blockIdx.x;
    const float* x  = x_all + (size_t)blk * (NTOK * CDIM);
    const float* mw = mask  + (size_t)(blk & (NWIN - 1)) * (NTOK * NTOK);

    // ---- load x transposed: s_xT[k][r] ----
    for (int idx = tid; idx < NTOK * CDIM; idx += TPB) {
        const int r = idx >> 7;
        const int k = idx & 127;
        s_xT[k * 52 + r] = x[idx];
    }
    __syncthreads();

    const int col   = tid & 127;
    const int g     = tid >> 7;       // 0..3
    const int rbase = g * 12;         // 0,12,24,36
    const int rcnt  = (g == 3) ? 13 : 12;

    // ---- phase 1: QKV GEMM, f32x2 row-paired accumulators ----
    {
        u64 a0[6], a1[6], a2[6];           // row pairs (rbase+2p, rbase+2p+1)
        float s0 = 0.f, s1 = 0.f, s2 = 0.f; // row rbase+12
        #pragma unroll
        for (int p = 0; p < 6; ++p) { a0[p] = 0ull; a1[p] = 0ull; a2[p] = 0ull; }

        #pragma unroll 2
        for (int kk = 0; kk < 128; ++kk) {
            const float* wr = qkv_w + (size_t)kk * 384;
            const float w0 = __ldg(&wr[col]);
            const float w1 = __ldg(&wr[128 + col]);
            const float w2 = __ldg(&wr[256 + col]);
            const u64 w0p = pack2(w0, w0);
            const u64 w1p = pack2(w1, w1);
            const u64 w2p = pack2(w2, w2);

            const ulonglong2* xr = reinterpret_cast<const ulonglong2*>(&s_xT[kk * 52 + rbase]);
            const ulonglong2 p01 = xr[0];   // rows +0..+3
            const ulonglong2 p23 = xr[1];   // rows +4..+7
            const ulonglong2 p45 = xr[2];   // rows +8..+11
            const float x12 = s_xT[kk * 52 + rbase + 12];

            fma2(a0[0], p01.x, w0p); fma2(a0[1], p01.y, w0p);
            fma2(a0[2], p23.x, w0p); fma2(a0[3], p23.y, w0p);
            fma2(a0[4], p45.x, w0p); fma2(a0[5], p45.y, w0p);
            fma2(a1[0], p01.x, w1p); fma2(a1[1], p01.y, w1p);
            fma2(a1[2], p23.x, w1p); fma2(a1[3], p23.y, w1p);
            fma2(a1[4], p45.x, w1p); fma2(a1[5], p45.y, w1p);
            fma2(a2[0], p01.x, w2p); fma2(a2[1], p01.y, w2p);
            fma2(a2[2], p23.x, w2p); fma2(a2[3], p23.y, w2p);
            fma2(a2[4], p45.x, w2p); fma2(a2[5], p45.y, w2p);
            s0 += x12 * w0;  s1 += x12 * w1;  s2 += x12 * w2;
        }

        const float b0 = __ldg(&qkv_b[col]);
        const float b1 = __ldg(&qkv_b[128 + col]);
        const float b2 = __ldg(&qkv_b[256 + col]);
        #pragma unroll
        for (int p = 0; p < 6; ++p) {
            const int r = rbase + 2 * p;
            const float2 f0 = unpack2(a0[p]);
            const float2 f1 = unpack2(a1[p]);
            const float2 f2 = unpack2(a2[p]);
            s_q[r * QPITCH + col]       = f0.x + b0;
            s_q[(r + 1) * QPITCH + col] = f0.y + b0;
            s_kT[col * 52 + r]          = f1.x + b1;
            s_kT[col * 52 + r + 1]      = f1.y + b1;
            s_v[r * 128 + col]          = f2.x + b2;
            s_v[(r + 1) * 128 + col]    = f2.y + b2;
        }
        if (rcnt == 13) {
            const int r = rbase + 12;
            s_q[r * QPITCH + col] = s0 + b0;
            s_kT[col * 52 + r]    = s1 + b1;
            s_v[r * 128 + col]    = s2 + b2;
        }
    }
    __syncthreads();

    // ---- phase 2: scores + bias + mask; thread = (h, row-pair, 4 adjacent j) ----
    {
        const float scale = 0.17677669529663687f;   // 1/sqrt(32)
        for (int u = tid; u < NHEAD * 25 * 13; u += TPB) {
            const int h   = u / (25 * 13);
            const int rem = u - h * (25 * 13);
            const int ib  = rem / 13;
            const int jg  = rem - ib * 13;
            const int j4  = jg * 4;
            const int i0  = ib;
            const bool has1 = (ib < 24);
            const int i1  = has1 ? ib + 25 : ib;   // duplicate work when no partner

            const float* q0 = &s_q[i0 * QPITCH + h * HDIM];
            const float* q1 = &s_q[i1 * QPITCH + h * HDIM];
            const float* kc = &s_kT[(h * HDIM) * 52 + j4];

            u64 acc0a = 0ull, acc0b = 0ull, acc1a = 0ull, acc1b = 0ull;
            #pragma unroll
            for (int d = 0; d < HDIM; ++d) {
                const ulonglong2 kv = *reinterpret_cast<const ulonglong2*>(&kc[d * 52]);
                const float qv0 = q0[d];
                const float qv1 = q1[d];
                const u64 q0p = pack2(qv0, qv0);
                const u64 q1p = pack2(qv1, qv1);
                fma2(acc0a, kv.x, q0p); fma2(acc0b, kv.y, q0p);
                fma2(acc1a, kv.x, q1p); fma2(acc1b, kv.y, q1p);
            }
            const float2 r0a = unpack2(acc0a), r0b = unpack2(acc0b);
            const float2 r1a = unpack2(acc1a), r1b = unpack2(acc1b);
            float sv0[4] = {r0a.x, r0a.y, r0b.x, r0b.y};
            float sv1[4] = {r1a.x, r1a.y, r1b.x, r1b.y};

            const int yi0 = i0 / 7, xi0 = i0 - yi0 * 7;
            const int yi1 = i1 / 7, xi1 = i1 - yi1 * 7;
            float* arow0 = &s_attn[(h * NTOK + i0) * 52];
            float* arow1 = &s_attn[(h * NTOK + i1) * 52];
            const float* mrow0 = &mw[i0 * NTOK];
            const float* mrow1 = &mw[i1 * NTOK];
            #pragma unroll
            for (int jj = 0; jj < 4; ++jj) {
                const int j = j4 + jj;
                if (j < NTOK) {
                    const int yj = j / 7, xj = j - yj * 7;
                    const int r0 = (yi0 - yj + 6) * 13 + (xi0 - xj + 6);
                    arow0[j] = sv0[jj] * scale + __ldg(&rel_table[r0 * NHEAD + h]) + mrow0[j];
                    if (has1) {
                        const int r1 = (yi1 - yj + 6) * 13 + (xi1 - xj + 6);
                        arow1[j] = sv1[jj] * scale + __ldg(&rel_table[r1 * NHEAD + h]) + mrow1[j];
                    }
                }
            }
        }
    }
    __syncthreads();

    // ---- phase 3: softmax, one warp per (head, query-row) ----
    {
        const int warp = tid >> 5;
        const int lane = tid & 31;
        for (int row = warp; row < NHEAD * NTOK; row += TPB / 32) {
            float* a = &s_attn[row * 52];
            float v0 = (lane < NTOK)      ? a[lane]      : -1e30f;
            float v1 = (lane + 32 < NTOK) ? a[lane + 32] : -1e30f;
            float m = fmaxf(v0, v1);
            #pragma unroll
            for (int off = 16; off; off >>= 1)
                m = fmaxf(m, __shfl_xor_sync(0xffffffffu, m, off));
            float e0 = (lane < NTOK)      ? __expf(v0 - m) : 0.f;
            float e1 = (lane + 32 < NTOK) ? __expf(v1 - m) : 0.f;
            float ssum = e0 + e1;
            #pragma unroll
            for (int off = 16; off; off >>= 1)
                ssum += __shfl_xor_sync(0xffffffffu, ssum, off);
            const float inv = 1.0f / ssum;
            if (lane < NTOK)      a[lane]      = e0 * inv;
            if (lane + 32 < NTOK) a[lane + 32] = e1 * inv;
        }
    }
    __syncthreads();

    // ---- phase 4: attn @ v; thread = (row-pair, 4 adjacent c) ----
    for (int u = tid; u < 25 * 32; u += TPB) {
        const int ib = u >> 5;
        const int cg = u & 31;
        const int c4 = cg * 4;
        const int h  = cg >> 3;
        const int i0 = ib;
        const bool has1 = (ib < 24);
        const int i1 = has1 ? ib + 25 : ib;

        const float* a0r = &s_attn[(h * NTOK + i0) * 52];
        const float* a1r = &s_attn[(h * NTOK + i1) * 52];
        const float* vr  = &s_v[c4];

        u64 o0a = 0ull, o0b = 0ull, o1a = 0ull, o1b = 0ull;
        #pragma unroll 7
        for (int j = 0; j < NTOK; ++j) {
            const ulonglong2 vv = *reinterpret_cast<const ulonglong2*>(&vr[j * 128]);
            const float av0 = a0r[j];
            const float av1 = a1r[j];
            const u64 a0p = pack2(av0, av0);
            const u64 a1p = pack2(av1, av1);
            fma2(o0a, vv.x, a0p); fma2(o0b, vv.y, a0p);
            fma2(o1a, vv.x, a1p); fma2(o1b, vv.y, a1p);
        }
        const float2 f0a = unpack2(o0a), f0b = unpack2(o0b);
        float4 w0; w0.x = f0a.x; w0.y = f0a.y; w0.z = f0b.x; w0.w = f0b.y;
        *reinterpret_cast<float4*>(&s_o[i0 * 128 + c4]) = w0;
        if (has1) {
            const float2 f1a = unpack2(o1a), f1b = unpack2(o1b);
            float4 w1; w1.x = f1a.x; w1.y = f1a.y; w1.z = f1b.x; w1.w = f1b.y;
            *reinterpret_cast<float4*>(&s_o[i1 * 128 + c4]) = w1;
        }
    }
    __syncthreads();

    // ---- phase 5: output projection, f32x2 k-paired ----
    {
        u64 acc[13];
        #pragma unroll
        for (int i = 0; i < 13; ++i) acc[i] = 0ull;

        #pragma unroll 2
        for (int k4 = 0; k4 < 32; ++k4) {
            const int kk = k4 * 4;
            const float w0 = __ldg(&proj_w[(size_t)(kk + 0) * 128 + col]);
            const float w1 = __ldg(&proj_w[(size_t)(kk + 1) * 128 + col]);
            const float w2 = __ldg(&proj_w[(size_t)(kk + 2) * 128 + col]);
            const float w3 = __ldg(&proj_w[(size_t)(kk + 3) * 128 + col]);
            const u64 w01 = pack2(w0, w1);
            const u64 w23 = pack2(w2, w3);
            #pragma unroll
            for (int i = 0; i < 13; ++i) {
                const ulonglong2 ov = *reinterpret_cast<const ulonglong2*>(&s_o[(rbase + i) * 128 + kk]);
                fma2(acc[i], ov.x, w01);
                fma2(acc[i], ov.y, w23);
            }
        }
        const float bv = __ldg(&proj_b[col]);
        float* o = out + (size_t)blk * (NTOK * CDIM);
        for (int i = 0; i < rcnt; ++i) {
            const float2 f = unpack2(acc[i]);
            o[(rbase + i) * 128 + col] = f.x + f.y + bv;
        }
    }
}

extern "C" void kernel_launch(void* const* d_in, const int* in_sizes, int n_in,
                              void* d_out, int out_size)
{
    const float* x      = (const float*)d_in[0];
    const float* mask   = (const float*)d_in[1];
    const float* qkv_w  = (const float*)d_in[2];
    const float* qkv_b  = (const float*)d_in[3];
    const float* proj_w = (const float*)d_in[4];
    const float* proj_b = (const float*)d_in[5];
    const float* rel    = (const float*)d_in[6];
    float* out = (float*)d_out;

    cudaFuncSetAttribute(swin_window_attn_kernel,
                         cudaFuncAttributeMaxDynamicSharedMemorySize, SMEM_BYTES);
    swin_window_attn_kernel<<<2048, TPB, SMEM_BYTES>>>(
        x, mask, qkv_w, qkv_b, proj_w, proj_b, rel, out);
}